// round 12
// baseline (speedup 1.0000x reference)
#include <cuda_runtime.h>
#include <cuda_fp16.h>
#include <cstdint>

#define N_ 2
#define LQ_ 4000
#define C_ 256
#define M_ 8
#define L_ 4
#define P_ 4
#define D_ 32
#define LIN_ 5440   // 64*64 + 32*32 + 16*16 + 8*8

// Scratch (static device globals; no allocation allowed)
__device__ __half g_kv [N_ * LIN_ * M_ * 64];  // [N,Lin,M,{k[32]|v[32]}]
__device__ float  g_q  [N_ * LQ_ * C_];
__device__ float  g_off[N_ * LQ_ * C_];
__device__ __half g_att[N_ * LQ_ * C_];
__device__ __half g_qh [N_ * LQ_ * C_];
__device__ __half g_inh[N_ * LIN_ * C_];
__device__ __half g_wh [5 * C_ * C_];          // Wk, Wv, Wq, Woff, Wout

// ---------------------------------------------------------------------------
// Single fused fp32 -> fp16 converter (7 tensors, grid.y selects)
// ---------------------------------------------------------------------------
struct CvtAll { const float* src[7]; __half* dst[7]; int n[7]; };
__global__ void f2h_all_kernel(CvtAll c) {
    const int which = blockIdx.y;
    const int i = (blockIdx.x * blockDim.x + threadIdx.x) * 4;
    if (i < c.n[which]) {
        float4 v = *reinterpret_cast<const float4*>(c.src[which] + i);
        __half2* p = reinterpret_cast<__half2*>(c.dst[which] + i);
        p[0] = __floats2half2_rn(v.x, v.y);
        p[1] = __floats2half2_rn(v.z, v.w);
    }
}

__device__ __forceinline__ uint32_t smem_u32(const void* p) {
    return static_cast<uint32_t>(__cvta_generic_to_shared(p));
}
__device__ __forceinline__ void cp16(uint32_t dst, const void* src) {
    asm volatile("cp.async.cg.shared.global [%0], [%1], 16;" :: "r"(dst), "l"(src));
}
__device__ __forceinline__ void cp_commit() {
    asm volatile("cp.async.commit_group;");
}
template<int NN>
__device__ __forceinline__ void cp_wait() {
    asm volatile("cp.async.wait_group %0;" :: "n"(NN));
}

// ---------------------------------------------------------------------------
// HMMA GEMM, fp16 inputs, 3-stage cp.async ring (ONE syncthreads per K-iter).
// Columns 0..255 use W, bias b0 -> out slot 0; 256..511 use W+65536, b1 -> 1.
// MODE 0: dual fp32 outs.  MODE 1: kv interleave (half).  MODE 2: single fp32.
// ---------------------------------------------------------------------------
template<int MODE>
__global__ __launch_bounds__(256) void gemm_mma(
    const __half* __restrict__ A, const __half* __restrict__ W,
    const float* __restrict__ b0, const float* __restrict__ b1,
    void* __restrict__ out0, void* __restrict__ out1, int rows)
{
    __shared__ __half As[3][128 * 40];
    __shared__ __half Bs[3][32 * 64];

    const int tid = threadIdx.x;
    const int lane = tid & 31;
    const int wm = (tid >> 5) & 3;
    const int wn = tid >> 7;
    const int row0 = blockIdx.y * 128;
    const int col0 = blockIdx.x * 64;
    const int wsel = col0 >> 8;
    const int colw = col0 & 255;

    const int ar = tid >> 2;
    const int ac = tid & 3;
    const __half* Ag0 = A + (size_t)min(row0 + ar,      rows - 1) * 256 + ac * 8;
    const __half* Ag1 = A + (size_t)min(row0 + ar + 64, rows - 1) * 256 + ac * 8;
    const uint32_t sA0 = smem_u32(&As[0][ar * 40 + ac * 8]);
    const uint32_t sA1 = smem_u32(&As[0][(ar + 64) * 40 + ac * 8]);
    const int bk = tid >> 3;
    const int bc = tid & 7;
    const __half* Bg = W + wsel * 65536 + (size_t)bk * 256 + colw + bc * 8;
    const uint32_t sB = smem_u32(&Bs[0][bk * 64 + ((bc ^ (bk & 7)) * 8)]);

    const uint32_t stA = 128 * 40 * 2;
    const uint32_t stB = 32 * 64 * 2;

    cp16(sA0, Ag0);
    cp16(sA1, Ag1);
    cp16(sB,  Bg);
    cp_commit();
    cp16(sA0 + stA, Ag0 + 32);
    cp16(sA1 + stA, Ag1 + 32);
    cp16(sB  + stB, Bg + (size_t)32 * 256);
    cp_commit();

    float acc[2][4][4];
#pragma unroll
    for (int mt = 0; mt < 2; mt++)
#pragma unroll
        for (int nt = 0; nt < 4; nt++)
#pragma unroll
            for (int i = 0; i < 4; i++) acc[mt][nt][i] = 0.0f;

    const int ltile = lane >> 3;
    const int ltr   = lane & 7;
    const int a_row_base = wm * 32 + (ltile & 1) * 8 + ltr;
    const int a_ch_off   = ltile >> 1;
    const int b_k_base   = (ltile & 1) * 8 + ltr;
    const int b_ch_off   = ltile >> 1;

#pragma unroll
    for (int it = 0; it < 8; it++) {
        cp_wait<1>();
        __syncthreads();

        const int ps = (it + 2) % 3;
        if (it < 6) {
            const int koff = (it + 2) * 32;
            cp16(sA0 + ps * stA, Ag0 + koff);
            cp16(sA1 + ps * stA, Ag1 + koff);
            cp16(sB  + ps * stB, Bg + (size_t)koff * 256);
        }
        cp_commit();

        const int buf = it % 3;
        const __half* Ab = As[buf];
        const __half* Bb = Bs[buf];
#pragma unroll
        for (int ks = 0; ks < 2; ks++) {
            uint32_t a[2][4], b[2][4];
#pragma unroll
            for (int mt = 0; mt < 2; mt++) {
                const int row = a_row_base + mt * 16;
                const int ch  = ks * 2 + a_ch_off;
                uint32_t addr = smem_u32(&Ab[row * 40 + ch * 8]);
                asm volatile(
                    "ldmatrix.sync.aligned.m8n8.x4.shared.b16 {%0,%1,%2,%3}, [%4];"
                    : "=r"(a[mt][0]), "=r"(a[mt][1]), "=r"(a[mt][2]), "=r"(a[mt][3])
                    : "r"(addr));
            }
#pragma unroll
            for (int p = 0; p < 2; p++) {
                const int k = ks * 16 + b_k_base;
                const int c = wn * 4 + p * 2 + b_ch_off;
                uint32_t addr = smem_u32(&Bb[k * 64 + ((c ^ (k & 7)) * 8)]);
                asm volatile(
                    "ldmatrix.sync.aligned.m8n8.x4.trans.shared.b16 {%0,%1,%2,%3}, [%4];"
                    : "=r"(b[p][0]), "=r"(b[p][1]), "=r"(b[p][2]), "=r"(b[p][3])
                    : "r"(addr));
            }
#pragma unroll
            for (int mt = 0; mt < 2; mt++)
#pragma unroll
                for (int nt = 0; nt < 4; nt++) {
                    const uint32_t bb0 = b[nt >> 1][(nt & 1) * 2 + 0];
                    const uint32_t bb1 = b[nt >> 1][(nt & 1) * 2 + 1];
                    asm volatile(
                        "mma.sync.aligned.m16n8k16.row.col.f32.f16.f16.f32 "
                        "{%0,%1,%2,%3}, {%4,%5,%6,%7}, {%8,%9}, {%0,%1,%2,%3};"
                        : "+f"(acc[mt][nt][0]), "+f"(acc[mt][nt][1]),
                          "+f"(acc[mt][nt][2]), "+f"(acc[mt][nt][3])
                        : "r"(a[mt][0]), "r"(a[mt][1]), "r"(a[mt][2]), "r"(a[mt][3]),
                          "r"(bb0), "r"(bb1));
                }
        }
    }

    const int g  = lane >> 2;
    const int qd = lane & 3;
    const float* bp = wsel ? b1 : b0;
#pragma unroll
    for (int mt = 0; mt < 2; mt++) {
        const int rlo = row0 + wm * 32 + mt * 16 + g;
        const int rhi = rlo + 8;
#pragma unroll
        for (int nt = 0; nt < 4; nt++) {
            const int n = col0 + wn * 32 + nt * 8 + qd * 2;
            const int c = n & 255;
            const float2 bb = *reinterpret_cast<const float2*>(&bp[c]);
            float v0 = acc[mt][nt][0] + bb.x, v1 = acc[mt][nt][1] + bb.y;
            float v2 = acc[mt][nt][2] + bb.x, v3 = acc[mt][nt][3] + bb.y;
            if (MODE == 1) {
                const int oc = ((c >> 5) << 6) + (c & 31) + (wsel ? 32 : 0);
                __half* o = (__half*)out0;
                if (rlo < rows)
                    *reinterpret_cast<__half2*>(&o[(size_t)rlo * 512 + oc]) = __floats2half2_rn(v0, v1);
                if (rhi < rows)
                    *reinterpret_cast<__half2*>(&o[(size_t)rhi * 512 + oc]) = __floats2half2_rn(v2, v3);
            } else {
                float* o = (MODE == 2) ? (float*)out0 : (wsel ? (float*)out1 : (float*)out0);
                if (rlo < rows)
                    *reinterpret_cast<float2*>(&o[(size_t)rlo * 256 + c]) = make_float2(v0, v1);
                if (rhi < rows)
                    *reinterpret_cast<float2*>(&o[(size_t)rhi * 256 + c]) = make_float2(v2, v3);
            }
        }
    }
}

// ---------------------------------------------------------------------------
// Sampling + key-aware attention. One warp per (n, q, m).
// Lane-per-point precompute: lane pt=lane&15 computes point pt's clamped
// corner indices + OOB-zeroed weights once; main loop broadcasts via shfl
// (8 shfls/point) and does unconditional straight-line gathers.
// Packed half2 pairwise reduction + no-max softmax (from R11).
// ---------------------------------------------------------------------------
__device__ __forceinline__ float2 ldkv(int hidx) {
    return __half22float2(*reinterpret_cast<const __half2*>(&g_kv[hidx]));
}

__global__ __launch_bounds__(256, 2) void sample_attn_kernel(
    const float* __restrict__ ref)   // [N, Lq, L, 2]
{
    const int w = blockIdx.x * 8 + (threadIdx.x >> 5);
    const int lane = threadIdx.x & 31;
    if (w >= N_ * LQ_ * M_) return;

    const int m  = w & 7;
    const int nq = w >> 3;
    const int n  = nq / LQ_;

    const int is_v = lane >> 4;
    const int cl = (lane & 15) * 2;

    float2 qd = make_float2(0.0f, 0.0f);
    if (!is_v) qd = *reinterpret_cast<const float2*>(&g_q[(nq * M_ + m) * D_ + cl]);

    const float* offp = g_off + nq * 256 + m * 32;
    const float* refp = ref + nq * 8;

    const int HWs[4]    = {64, 32, 16, 8};
    const int starts[4] = {0, 4096, 5120, 5376};
    const float SCALE = 0.17677669529663687f;   // 1/sqrt(32)

    // ---- per-lane point precompute (lane pt owns point pt) ----
    const int pt = lane & 15;
    const int pl = pt >> 2;                 // my point's level
    const int myHW = HWs[pl];
    const float fHW = (float)myHW;
    const float2 rr = *reinterpret_cast<const float2*>(&refp[pl * 2]);
    const float2 oo = *reinterpret_cast<const float2*>(&offp[pt * 2]);
    const float x = (rr.x * fHW - 0.5f) + oo.x;
    const float y = (rr.y * fHW - 0.5f) + oo.y;
    const float x0f = floorf(x), y0f = floorf(y);
    const float tx = x - x0f, ty = y - y0f;
    const int x0 = (int)x0f, y0 = (int)y0f;
    const unsigned uHW = (unsigned)myHW;
    const bool x0v = (unsigned)x0 < uHW, x1v = (unsigned)(x0 + 1) < uHW;
    const bool y0v = (unsigned)y0 < uHW, y1v = (unsigned)(y0 + 1) < uHW;
    const float wx0 = 1.0f - tx, wy0 = 1.0f - ty;
    const float pw00 = (x0v && y0v) ? wx0 * wy0 : 0.0f;
    const float pw10 = (x1v && y0v) ? tx  * wy0 : 0.0f;
    const float pw01 = (x0v && y1v) ? wx0 * ty  : 0.0f;
    const float pw11 = (x1v && y1v) ? tx  * ty  : 0.0f;
    const int HW2m1 = myHW * myHW - 1;
    const int ci = y0 * myHW + x0;
    const int pi00 = min(max(ci,             0), HW2m1);
    const int pi10 = min(max(ci + 1,         0), HW2m1);
    const int pi01 = min(max(ci + myHW,      0), HW2m1);
    const int pi11 = min(max(ci + myHW + 1,  0), HW2m1);

    // kv base for THIS lane at level 0 (halves); level l adds starts[l]*512
    const int kvb0 = ((n * LIN_) * M_ + m) * 64 + lane * 2;

    float logits[16], sv0[16], sv1[16];

#pragma unroll
    for (int pr = 0; pr < 8; pr++) {
        const int pa = pr * 2;
        const int pb = pa + 1;
        const int lvl = pa >> 2;
        const int bl = kvb0 + starts[lvl] * 512;

        // broadcast point A and B state (8 shfls per point)
        const int a00 = __shfl_sync(0xffffffffu, pi00, pa);
        const int a10 = __shfl_sync(0xffffffffu, pi10, pa);
        const int a01 = __shfl_sync(0xffffffffu, pi01, pa);
        const int a11 = __shfl_sync(0xffffffffu, pi11, pa);
        const int b00 = __shfl_sync(0xffffffffu, pi00, pb);
        const int b10 = __shfl_sync(0xffffffffu, pi10, pb);
        const int b01 = __shfl_sync(0xffffffffu, pi01, pb);
        const int b11 = __shfl_sync(0xffffffffu, pi11, pb);
        const float aw00 = __shfl_sync(0xffffffffu, pw00, pa);
        const float aw10 = __shfl_sync(0xffffffffu, pw10, pa);
        const float aw01 = __shfl_sync(0xffffffffu, pw01, pa);
        const float aw11 = __shfl_sync(0xffffffffu, pw11, pa);
        const float bw00 = __shfl_sync(0xffffffffu, pw00, pb);
        const float bw10 = __shfl_sync(0xffffffffu, pw10, pb);
        const float bw01 = __shfl_sync(0xffffffffu, pw01, pb);
        const float bw11 = __shfl_sync(0xffffffffu, pw11, pb);

        // 8 unconditional straight-line gathers (clamped = always legal)
        const float2 fA00 = ldkv(bl + a00 * 512);
        const float2 fA10 = ldkv(bl + a10 * 512);
        const float2 fA01 = ldkv(bl + a01 * 512);
        const float2 fA11 = ldkv(bl + a11 * 512);
        const float2 fB00 = ldkv(bl + b00 * 512);
        const float2 fB10 = ldkv(bl + b10 * 512);
        const float2 fB01 = ldkv(bl + b01 * 512);
        const float2 fB11 = ldkv(bl + b11 * 512);

        float a0 = aw00 * fA00.x, a1 = aw00 * fA00.y;
        float b0 = bw00 * fB00.x, b1 = bw00 * fB00.y;
        a0 = fmaf(aw10, fA10.x, a0); a1 = fmaf(aw10, fA10.y, a1);
        b0 = fmaf(bw10, fB10.x, b0); b1 = fmaf(bw10, fB10.y, b1);
        a0 = fmaf(aw01, fA01.x, a0); a1 = fmaf(aw01, fA01.y, a1);
        b0 = fmaf(bw01, fB01.x, b0); b1 = fmaf(bw01, fB01.y, b1);
        a0 = fmaf(aw11, fA11.x, a0); a1 = fmaf(aw11, fA11.y, a1);
        b0 = fmaf(bw11, fB11.x, b0); b1 = fmaf(bw11, fB11.y, b1);

        sv0[pa] = a0; sv1[pa] = a1;
        sv0[pb] = b0; sv1[pb] = b1;

        // scaled key partials; packed half2 reduction for both points at once
        float lgA = is_v ? 0.0f : fmaf(qd.x, a0, qd.y * a1) * SCALE;
        float lgB = is_v ? 0.0f : fmaf(qd.x, b0, qd.y * b1) * SCALE;
        __half2 hl = __floats2half2_rn(lgA, lgB);
#pragma unroll
        for (int s = 16; s > 0; s >>= 1) {
            uint32_t u = *reinterpret_cast<uint32_t*>(&hl);
            uint32_t v = __shfl_xor_sync(0xffffffffu, u, s);
            hl = __hadd2(hl, *reinterpret_cast<__half2*>(&v));
        }
        const float2 lf = __half22float2(hl);
        logits[pa] = lf.x;
        logits[pb] = lf.y;
    }

    // softmax (logits are O(0.1): no max-subtraction needed in fp32)
    float ssum = 0.0f;
#pragma unroll
    for (int i = 0; i < 16; i++) {
        logits[i] = __expf(logits[i]);
        ssum += logits[i];
    }
    const float inv = 1.0f / ssum;
    float o0 = 0.0f, o1 = 0.0f;
#pragma unroll
    for (int i = 0; i < 16; i++) {
        o0 = fmaf(logits[i], sv0[i], o0);
        o1 = fmaf(logits[i], sv1[i], o1);
    }

    if (is_v)
        *reinterpret_cast<__half2*>(&g_att[(nq * M_ + m) * D_ + cl]) =
            __floats2half2_rn(o0 * inv, o1 * inv);
}

// ---------------------------------------------------------------------------
extern "C" void kernel_launch(void* const* d_in, const int* in_sizes, int n_in,
                              void* d_out, int out_size)
{
    const float* query = (const float*)d_in[0];
    const float* ref   = (const float*)d_in[1];
    const float* inp   = (const float*)d_in[2];
    const float* Wv   = (const float*)d_in[5];
    const float* bv   = (const float*)d_in[6];
    const float* Wk   = (const float*)d_in[7];
    const float* bk   = (const float*)d_in[8];
    const float* Wq   = (const float*)d_in[9];
    const float* bq   = (const float*)d_in[10];
    const float* Woff = (const float*)d_in[11];
    const float* boff = (const float*)d_in[12];
    const float* Wout = (const float*)d_in[13];
    const float* bout = (const float*)d_in[14];
    float* out = (float*)d_out;

    void *pkv, *pq, *po, *pa, *pqh, *pinh, *pwh;
    cudaGetSymbolAddress(&pkv,  g_kv);
    cudaGetSymbolAddress(&pq,   g_q);
    cudaGetSymbolAddress(&po,   g_off);
    cudaGetSymbolAddress(&pa,   g_att);
    cudaGetSymbolAddress(&pqh,  g_qh);
    cudaGetSymbolAddress(&pinh, g_inh);
    cudaGetSymbolAddress(&pwh,  g_wh);

    const int rowsV = N_ * LIN_;   // 10880
    const int rowsQ = N_ * LQ_;    // 8000
    const int gyV = rowsV / 128;          // 85
    const int gyQ = (rowsQ + 127) / 128;  // 63

    const int nQ = rowsQ * 256;
    const int nV = rowsV * 256;

    __half* wh = (__half*)pwh;
    CvtAll ca;
    ca.src[0] = inp;   ca.dst[0] = (__half*)pinh; ca.n[0] = nV;
    ca.src[1] = query; ca.dst[1] = (__half*)pqh;  ca.n[1] = nQ;
    const float* wsrc[5] = {Wk, Wv, Wq, Woff, Wout};
    for (int i = 0; i < 5; i++) {
        ca.src[2 + i] = wsrc[i];
        ca.dst[2 + i] = wh + i * 65536;
        ca.n[2 + i] = 65536;
    }
    f2h_all_kernel<<<dim3((nV / 4 + 255) / 256, 7), 256>>>(ca);

    gemm_mma<1><<<dim3(8, gyV), 256>>>((const __half*)pinh, wh + 0 * 65536,
                                       bk, bv, pkv, nullptr, rowsV);
    gemm_mma<0><<<dim3(8, gyQ), 256>>>((const __half*)pqh, wh + 2 * 65536,
                                       bq, boff, pq, po, rowsQ);

    const int nwarps = N_ * LQ_ * M_;          // 64000
    sample_attn_kernel<<<(nwarps + 7) / 8, 256>>>(ref);

    gemm_mma<2><<<dim3(4, gyQ), 256>>>((const __half*)pa, wh + 4 * 65536,
                                       bout, bout, out, nullptr, rowsQ);
}